// round 14
// baseline (speedup 1.0000x reference)
#include <cuda_runtime.h>
#include <math.h>

#define NPTS  1024
#define D2    256
#define D3    512
#define CELLS 64
#define SBCNT 128

__device__ float g_hsum[SBCNT * CELLS * D2];
__device__ int   g_cnt [SBCNT * CELLS];

__constant__ float c_freq[8] = {
    1.0f, 1.7782794100389228f, 3.1622776601683795f, 5.623413251903491f,
    10.0f, 17.782794100389228f, 31.622776601683793f, 56.23413251903491f
};

typedef unsigned long long u64;

__device__ __forceinline__ u64 pk2(float lo, float hi) {
    u64 r; asm("mov.b64 %0,{%1,%2};" : "=l"(r) : "f"(lo), "f"(hi)); return r;
}
__device__ __forceinline__ u64 dup2(float v) { return pk2(v, v); }
__device__ __forceinline__ u64 ffma2(u64 a, u64 b, u64 c) {
    u64 d; asm("fma.rn.f32x2 %0,%1,%2,%3;" : "=l"(d) : "l"(a), "l"(b), "l"(c)); return d;
}
__device__ __forceinline__ u64 fadd2(u64 a, u64 b) {
    u64 d; asm("add.rn.f32x2 %0,%1,%2;" : "=l"(d) : "l"(a), "l"(b)); return d;
}
__device__ __forceinline__ float2 un2(u64 v) {
    float2 f; asm("mov.b64 {%0,%1},%2;" : "=f"(f.x), "=f"(f.y) : "l"(v)); return f;
}
// silu via 1 MUFU: x*sigmoid(x) = 0.5x*(1+tanh(0.5x))
__device__ __forceinline__ float silu_f(float v) {
    float h = 0.5f * v;
    float t; asm("tanh.approx.f32 %0, %1;" : "=f"(t) : "f"(h));
    return __fmaf_rn(h, t, h);
}
__device__ __forceinline__ u64 silu2(u64 a) {
    float2 v = un2(a); return pk2(silu_f(v.x), silu_f(v.y));
}
// Cody-Waite mod-2pi then MUFU trig (arg reduced to [-pi,pi])
__device__ __forceinline__ float trig_red(float arg, int use_cos) {
    const float INV2PI = 0.15915494309189535f;
    const float C_HI   = 6.2831854820251465f;
    const float C_LO   = -1.7484556e-7f;
    float q = rintf(arg * INV2PI);
    float r = __fmaf_rn(-q, C_HI, arg);
    r = __fmaf_rn(-q, C_LO, r);
    return use_cos ? __cosf(r) : __sinf(r);
}

__device__ __forceinline__ unsigned smem_u32(const void* p) {
    return (unsigned)__cvta_generic_to_shared(p);
}
__device__ __forceinline__ void cpa16(unsigned s, const void* g) {
    asm volatile("cp.async.cg.shared.global [%0], [%1], 16;" :: "r"(s), "l"(g));
}
__device__ __forceinline__ void pair_bar(int id) {
    asm volatile("bar.sync %0, 64;" :: "r"(id) : "memory");
}

// ---------------- K1 smem layout (bytes) — R12 structure ----------------
#define S1_W2    0          // 131072
#define S1_W1    131072     // 16384
#define S1_H1    147456     // 65536  (8 pairs * 16 pts * 128 f; fts aliases)
#define S1_ORD   212992     // 2048   (u16[1024])
#define S1_CSORT 215040     // 1024   (u8[1024])
#define S1_CNT   216064     // 256
#define S1_START 216320     // 272
#define S1_CUR   216592     // 256
#define SMEM1    216848

__global__ __launch_bounds__(512, 1)
void k1_embed_agg(const float* __restrict__ ds, const float* __restrict__ de,
                  const float* __restrict__ W1, const float* __restrict__ b1,
                  const float* __restrict__ W2, const float* __restrict__ b2)
{
    extern __shared__ char smem[];
    float*          W2s    = (float*)(smem + S1_W2);
    float*          W1s    = (float*)(smem + S1_W1);
    float*          h1s    = (float*)(smem + S1_H1);
    unsigned short* ordsm  = (unsigned short*)(smem + S1_ORD);
    unsigned char*  csort  = (unsigned char*)(smem + S1_CSORT);
    unsigned*       cntsm  = (unsigned*)(smem + S1_CNT);
    unsigned*       startsm= (unsigned*)(smem + S1_START);
    unsigned*       cursm  = (unsigned*)(smem + S1_CUR);

    const int tid = threadIdx.x;
    const int w   = tid >> 5;
    const int l   = tid & 31;
    const int sb  = blockIdx.x;
    const int side = sb >> 6;
    const int bv   = sb & 63;
    const float* __restrict__ drags = (side ? de : ds) + (size_t)bv * NPTS * 2;
    float* gbase = g_hsum + (size_t)sb * CELLS * D2;

    {
        const float4* src2 = (const float4*)W2;
        float4* dst2 = (float4*)W2s;
        #pragma unroll 4
        for (int i = tid; i < (128 * 256) / 4; i += 512) dst2[i] = src2[i];
        const float4* src1 = (const float4*)W1;
        float4* dst1 = (float4*)W1s;
        #pragma unroll
        for (int i = tid; i < (32 * 128) / 4; i += 512) dst1[i] = src1[i];
        float4* gz = (float4*)gbase;
        #pragma unroll
        for (int i = tid; i < (CELLS * D2) / 4; i += 512)
            gz[i] = make_float4(0.f, 0.f, 0.f, 0.f);
        if (tid < 64) cntsm[tid] = 0u;
    }
    __syncthreads();

    #pragma unroll
    for (int i = tid; i < NPTS; i += 512) {
        float2 xy = *(const float2*)(drags + 2 * i);
        unsigned cell = (unsigned)((((int)xy.x) >> 6) * 8 + (((int)xy.y) >> 6));
        atomicAdd(&cntsm[cell], 1u);
    }
    __syncthreads();
    if (tid == 0) {
        unsigned run = 0;
        for (int c = 0; c < CELLS; c++) { startsm[c] = run; run += cntsm[c]; }
        startsm[CELLS] = run;
    }
    __syncthreads();
    if (tid < 64) {
        cursm[tid] = startsm[tid];
        g_cnt[sb * CELLS + tid] = (int)cntsm[tid];
    }
    __syncthreads();
    #pragma unroll
    for (int i = tid; i < NPTS; i += 512) {
        float2 xy = *(const float2*)(drags + 2 * i);
        unsigned cell = (unsigned)((((int)xy.x) >> 6) * 8 + (((int)xy.y) >> 6));
        unsigned pos = atomicAdd(&cursm[cell], 1u);
        ordsm[pos] = (unsigned short)i;
        csort[pos] = (unsigned char)cell;
    }
    __syncthreads();

    const int pairid = w >> 1;
    const int half   = w & 1;
    float* htile = h1s + pairid * 2048;        // 16 rows x 128 f
    float* myfts = htile + half * 1024;        // aliases own 8 rows

    u64 b1r0 = *(const u64*)(b1 + 4 * l);
    u64 b1r1 = *(const u64*)(b1 + 4 * l + 2);
    const int colbase = 128 * half + 4 * l;
    u64 b2ra = *(const u64*)(b2 + colbase);
    u64 b2rb = *(const u64*)(b2 + colbase + 2);

    const float fr      = c_freq[l >> 2];
    const int   use_y   = l & 1;
    const int   use_cos = (l >> 1) & 1;
    const int   barid   = 1 + pairid;

    u64 run0 = 0, run1 = 0;
    int cur_cell = -1;

    #pragma unroll 1
    for (int b = 0; b < 8; b++) {
        const int p0 = 128 * pairid + 16 * b;

        float fv[8];
        #pragma unroll
        for (int pp = 0; pp < 8; pp++) {
            int idx = (int)ordsm[p0 + 8 * half + pp];
            float2 xy = *(const float2*)(drags + 2 * idx);
            fv[pp] = trig_red((use_y ? xy.y : xy.x) * fr, use_cos);
        }
        #pragma unroll
        for (int pp = 0; pp < 8; pp++) myfts[pp * 32 + l] = fv[pp];
        __syncwarp();

        u64 a1[8][2];
        #pragma unroll
        for (int pp = 0; pp < 8; pp++) { a1[pp][0] = b1r0; a1[pp][1] = b1r1; }
        #pragma unroll 4
        for (int k2 = 0; k2 < 16; k2++) {
            float2 f01[8];
            #pragma unroll
            for (int pp = 0; pp < 8; pp++)
                f01[pp] = *(const float2*)(myfts + pp * 32 + 2 * k2);
            #pragma unroll
            for (int s = 0; s < 2; s++) {
                const int k = 2 * k2 + s;
                ulonglong2 wv = *(const ulonglong2*)(W1s + k * 128 + 4 * l);
                #pragma unroll
                for (int pp = 0; pp < 8; pp++) {
                    u64 f2 = dup2(s ? f01[pp].y : f01[pp].x);
                    a1[pp][0] = ffma2(f2, wv.x, a1[pp][0]);
                    a1[pp][1] = ffma2(f2, wv.y, a1[pp][1]);
                }
            }
        }
        __syncwarp();
        #pragma unroll
        for (int pp = 0; pp < 8; pp++) {
            float2 v0 = un2(a1[pp][0]), v1 = un2(a1[pp][1]);
            float4 hv = make_float4(silu_f(v0.x), silu_f(v0.y),
                                    silu_f(v1.x), silu_f(v1.y));
            *(float4*)(htile + (8 * half + pp) * 128 + 4 * l) = hv;
        }
        pair_bar(barid);

        u64 acc[16][2];
        #pragma unroll
        for (int pp = 0; pp < 16; pp++) { acc[pp][0] = b2ra; acc[pp][1] = b2rb; }
        #pragma unroll 1
        for (int kq = 0; kq < 32; kq++) {
            const float* wr = W2s + (4 * kq) * 256 + colbase;
            ulonglong2 wv0 = *(const ulonglong2*)(wr);
            ulonglong2 wv1 = *(const ulonglong2*)(wr + 256);
            ulonglong2 wv2 = *(const ulonglong2*)(wr + 512);
            ulonglong2 wv3 = *(const ulonglong2*)(wr + 768);
            const float* hb = htile + 4 * kq;
            #pragma unroll
            for (int pp = 0; pp < 16; pp++) {
                float4 h4 = *(const float4*)(hb + pp * 128);
                acc[pp][0] = ffma2(dup2(h4.x), wv0.x, acc[pp][0]);
                acc[pp][1] = ffma2(dup2(h4.x), wv0.y, acc[pp][1]);
                acc[pp][0] = ffma2(dup2(h4.y), wv1.x, acc[pp][0]);
                acc[pp][1] = ffma2(dup2(h4.y), wv1.y, acc[pp][1]);
                acc[pp][0] = ffma2(dup2(h4.z), wv2.x, acc[pp][0]);
                acc[pp][1] = ffma2(dup2(h4.z), wv2.y, acc[pp][1]);
                acc[pp][0] = ffma2(dup2(h4.w), wv3.x, acc[pp][0]);
                acc[pp][1] = ffma2(dup2(h4.w), wv3.y, acc[pp][1]);
            }
        }

        #pragma unroll
        for (int pp = 0; pp < 16; pp++) {
            int c = (int)csort[p0 + pp];
            if (c != cur_cell) {
                if (cur_cell >= 0) {
                    float* gp = gbase + (size_t)cur_cell * D2 + colbase;
                    float2 v0 = un2(run0), v1 = un2(run1);
                    atomicAdd(gp,     v0.x); atomicAdd(gp + 1, v0.y);
                    atomicAdd(gp + 2, v1.x); atomicAdd(gp + 3, v1.y);
                }
                cur_cell = c;
                run0 = run1 = 0;
            }
            run0 = fadd2(run0, silu2(acc[pp][0]));
            run1 = fadd2(run1, silu2(acc[pp][1]));
        }
        pair_bar(barid);
    }
    if (cur_cell >= 0) {
        float* gp = gbase + (size_t)cur_cell * D2 + colbase;
        float2 v0 = un2(run0), v1 = un2(run1);
        atomicAdd(gp,     v0.x); atomicAdd(gp + 1, v0.y);
        atomicAdd(gp + 2, v1.x); atomicAdd(gp + 3, v1.y);
    }
}

// ---------------- K2: 256 blocks x 256 thr, col-split halves, 2/SM ----------------
#define S2_W3A 0        // 16384 (16 rows * 256 f)
#define S2_W3B 16384    // 16384
#define S2_HST 32768    // 66560 (256 * 65 f, padded transpose)
#define S2_B3  99328    // 1024  (this block's 256 cols)
#define S2_CNT 100352   // 256
#define SMEM2  100608

// block (sb, ch): out[sb, cols 256ch..256ch+256) = Hsum[sb] @ W3[:,cols] + cnt*b3
// 8 warps: warp w owns cols [256ch+32w, +32); lane l owns cells l, l+32.
__global__ __launch_bounds__(256, 2)
void k2_l3(const float* __restrict__ W3, const float* __restrict__ b3,
           float* __restrict__ out)
{
    extern __shared__ char smem[];
    float* w3a  = (float*)(smem + S2_W3A);
    float* w3b  = (float*)(smem + S2_W3B);
    float* Hst  = (float*)(smem + S2_HST);
    float* b3s  = (float*)(smem + S2_B3);
    float* cnts = (float*)(smem + S2_CNT);

    const int tid = threadIdx.x;
    const int w   = tid >> 5;
    const int l   = tid & 31;
    const int sb  = blockIdx.x & 127;
    const int ch  = blockIdx.x >> 7;
    const int side = sb >> 6;
    const int bv   = sb & 63;
    const int cb   = 256 * ch;          // this block's first column

    const unsigned sa = smem_u32(w3a);
    const unsigned sbuf[2] = { sa, sa + 16384u };

    // prefetch W3 tile 0: rows [0,16), cols [cb, cb+256) = 1024 float4
    {
        #pragma unroll
        for (int j = 0; j < 4; j++) {
            int f4 = tid + j * 256;
            int r  = f4 >> 6;               // 64 float4 per row
            int cq = f4 & 63;
            cpa16(sbuf[0] + f4 * 16, W3 + (size_t)r * D3 + cb + 4 * cq);
        }
        asm volatile("cp.async.commit_group;");
    }

    // stage transposed H: Hst[k*65 + cell] = g_hsum[sb][cell][k]
    {
        const float* src = g_hsum + (size_t)sb * CELLS * D2;
        #pragma unroll
        for (int base = tid; base < CELLS * D2; base += 256) {
            int cell = base >> 8;
            int k    = base & 255;
            Hst[k * 65 + cell] = src[base];
        }
        b3s[tid] = b3[cb + tid];
        if (tid < 64) cnts[tid] = (float)g_cnt[sb * CELLS + tid];
    }

    u64 acc[2][16];
    #pragma unroll
    for (int h = 0; h < 2; h++)
        #pragma unroll
        for (int j = 0; j < 16; j++) acc[h][j] = 0ull;

    #pragma unroll 1
    for (int kt = 0; kt < 16; kt++) {
        if (kt < 15) {   // prefetch next 16-row tile into other buffer
            const float* gn = W3 + (size_t)(kt + 1) * 16 * D3 + cb;
            #pragma unroll
            for (int j = 0; j < 4; j++) {
                int f4 = tid + j * 256;
                int r  = f4 >> 6;
                int cq = f4 & 63;
                cpa16(sbuf[(kt + 1) & 1] + f4 * 16, gn + (size_t)r * D3 + 4 * cq);
            }
            asm volatile("cp.async.commit_group;");
            asm volatile("cp.async.wait_group 1;");
        } else {
            asm volatile("cp.async.wait_group 0;");
        }
        __syncthreads();

        const float* wt = (kt & 1) ? w3b : w3a;
        #pragma unroll 2
        for (int kk = 0; kk < 16; kk++) {
            const int k = kt * 16 + kk;
            u64 hd0 = dup2(Hst[k * 65 + l]);
            u64 hd1 = dup2(Hst[k * 65 + l + 32]);
            const float* wr = wt + kk * 256 + 32 * w;
            #pragma unroll
            for (int j2 = 0; j2 < 8; j2++) {   // broadcast LDS.128
                ulonglong2 wv = *(const ulonglong2*)(wr + 4 * j2);
                acc[0][2 * j2]     = ffma2(hd0, wv.x, acc[0][2 * j2]);
                acc[0][2 * j2 + 1] = ffma2(hd0, wv.y, acc[0][2 * j2 + 1]);
                acc[1][2 * j2]     = ffma2(hd1, wv.x, acc[1][2 * j2]);
                acc[1][2 * j2 + 1] = ffma2(hd1, wv.y, acc[1][2 * j2 + 1]);
            }
        }
        __syncthreads();   // protect buffer before next prefetch overwrites
    }

    const float c0 = cnts[l], c1 = cnts[l + 32];
    float* outp = out + ((size_t)(bv * 1024 + side * 512)) * 64;
    #pragma unroll
    for (int j = 0; j < 16; j++) {
        int lcol = 32 * w + 2 * j;
        int col  = cb + lcol;
        float bx = b3s[lcol], by = b3s[lcol + 1];
        float2 v0 = un2(acc[0][j]);
        float2 v1 = un2(acc[1][j]);
        outp[(size_t)col       * 64 + l]      = v0.x + c0 * bx;
        outp[(size_t)(col + 1) * 64 + l]      = v0.y + c0 * by;
        outp[(size_t)col       * 64 + l + 32] = v1.x + c1 * bx;
        outp[(size_t)(col + 1) * 64 + l + 32] = v1.y + c1 * by;
    }
}

extern "C" void kernel_launch(void* const* d_in, const int* in_sizes, int n_in,
                              void* d_out, int out_size)
{
    const float* ds = (const float*)d_in[0];
    const float* de = (const float*)d_in[1];
    const float* W1 = (const float*)d_in[2];
    const float* b1 = (const float*)d_in[3];
    const float* W2 = (const float*)d_in[4];
    const float* b2 = (const float*)d_in[5];
    const float* W3 = (const float*)d_in[6];
    const float* b3 = (const float*)d_in[7];
    float* out = (float*)d_out;

    cudaFuncSetAttribute(k1_embed_agg, cudaFuncAttributeMaxDynamicSharedMemorySize, SMEM1);
    cudaFuncSetAttribute(k2_l3,        cudaFuncAttributeMaxDynamicSharedMemorySize, SMEM2);

    k1_embed_agg<<<SBCNT, 512, SMEM1>>>(ds, de, W1, b1, W2, b2);
    k2_l3<<<2 * SBCNT, 256, SMEM2>>>(W3, b3, out);
}

// round 15
// speedup vs baseline: 1.5114x; 1.5114x over previous
#include <cuda_runtime.h>
#include <math.h>

#define NPTS  1024
#define D2    256
#define D3    512
#define CELLS 64
#define SBCNT 128

__device__ float g_hsum[SBCNT * CELLS * D2];
__device__ int   g_cnt [SBCNT * CELLS];

__constant__ float c_freq[8] = {
    1.0f, 1.7782794100389228f, 3.1622776601683795f, 5.623413251903491f,
    10.0f, 17.782794100389228f, 31.622776601683793f, 56.23413251903491f
};

typedef unsigned long long u64;

__device__ __forceinline__ u64 pk2(float lo, float hi) {
    u64 r; asm("mov.b64 %0,{%1,%2};" : "=l"(r) : "f"(lo), "f"(hi)); return r;
}
__device__ __forceinline__ u64 dup2(float v) { return pk2(v, v); }
__device__ __forceinline__ u64 ffma2(u64 a, u64 b, u64 c) {
    u64 d; asm("fma.rn.f32x2 %0,%1,%2,%3;" : "=l"(d) : "l"(a), "l"(b), "l"(c)); return d;
}
__device__ __forceinline__ u64 fadd2(u64 a, u64 b) {
    u64 d; asm("add.rn.f32x2 %0,%1,%2;" : "=l"(d) : "l"(a), "l"(b)); return d;
}
__device__ __forceinline__ float2 un2(u64 v) {
    float2 f; asm("mov.b64 {%0,%1},%2;" : "=f"(f.x), "=f"(f.y) : "l"(v)); return f;
}
// silu via 1 MUFU: x*sigmoid(x) = 0.5x*(1+tanh(0.5x))
__device__ __forceinline__ float silu_f(float v) {
    float h = 0.5f * v;
    float t; asm("tanh.approx.f32 %0, %1;" : "=f"(t) : "f"(h));
    return __fmaf_rn(h, t, h);
}
__device__ __forceinline__ u64 silu2(u64 a) {
    float2 v = un2(a); return pk2(silu_f(v.x), silu_f(v.y));
}
// Cody-Waite mod-2pi then MUFU trig (arg reduced to [-pi,pi])
__device__ __forceinline__ float trig_red(float arg, int use_cos) {
    const float INV2PI = 0.15915494309189535f;
    const float C_HI   = 6.2831854820251465f;
    const float C_LO   = -1.7484556e-7f;
    float q = rintf(arg * INV2PI);
    float r = __fmaf_rn(-q, C_HI, arg);
    r = __fmaf_rn(-q, C_LO, r);
    return use_cos ? __cosf(r) : __sinf(r);
}

__device__ __forceinline__ unsigned smem_u32(const void* p) {
    return (unsigned)__cvta_generic_to_shared(p);
}
__device__ __forceinline__ void cpa16(unsigned s, const void* g) {
    asm volatile("cp.async.cg.shared.global [%0], [%1], 16;" :: "r"(s), "l"(g));
}
__device__ __forceinline__ void pair_bar(int id) {
    asm volatile("bar.sync %0, 64;" :: "r"(id) : "memory");
}

// ---------------- K1 smem layout (bytes) — R12 structure ----------------
#define S1_W2    0          // 131072
#define S1_W1    131072     // 16384
#define S1_H1    147456     // 65536  (8 pairs * 16 pts * 128 f; fts aliases)
#define S1_ORD   212992     // 2048   (u16[1024])
#define S1_CSORT 215040     // 1024   (u8[1024])
#define S1_CNT   216064     // 256
#define S1_START 216320     // 272
#define S1_CUR   216592     // 256
#define SMEM1    216848

__global__ __launch_bounds__(512, 1)
void k1_embed_agg(const float* __restrict__ ds, const float* __restrict__ de,
                  const float* __restrict__ W1, const float* __restrict__ b1,
                  const float* __restrict__ W2, const float* __restrict__ b2)
{
    extern __shared__ char smem[];
    float*          W2s    = (float*)(smem + S1_W2);
    float*          W1s    = (float*)(smem + S1_W1);
    float*          h1s    = (float*)(smem + S1_H1);
    unsigned short* ordsm  = (unsigned short*)(smem + S1_ORD);
    unsigned char*  csort  = (unsigned char*)(smem + S1_CSORT);
    unsigned*       cntsm  = (unsigned*)(smem + S1_CNT);
    unsigned*       startsm= (unsigned*)(smem + S1_START);
    unsigned*       cursm  = (unsigned*)(smem + S1_CUR);

    const int tid = threadIdx.x;
    const int w   = tid >> 5;
    const int l   = tid & 31;
    const int sb  = blockIdx.x;
    const int side = sb >> 6;
    const int bv   = sb & 63;
    const float* __restrict__ drags = (side ? de : ds) + (size_t)bv * NPTS * 2;
    float* gbase = g_hsum + (size_t)sb * CELLS * D2;

    {
        const float4* src2 = (const float4*)W2;
        float4* dst2 = (float4*)W2s;
        #pragma unroll 4
        for (int i = tid; i < (128 * 256) / 4; i += 512) dst2[i] = src2[i];
        const float4* src1 = (const float4*)W1;
        float4* dst1 = (float4*)W1s;
        #pragma unroll
        for (int i = tid; i < (32 * 128) / 4; i += 512) dst1[i] = src1[i];
        float4* gz = (float4*)gbase;
        #pragma unroll
        for (int i = tid; i < (CELLS * D2) / 4; i += 512)
            gz[i] = make_float4(0.f, 0.f, 0.f, 0.f);
        if (tid < 64) cntsm[tid] = 0u;
    }
    __syncthreads();

    #pragma unroll
    for (int i = tid; i < NPTS; i += 512) {
        float2 xy = *(const float2*)(drags + 2 * i);
        unsigned cell = (unsigned)((((int)xy.x) >> 6) * 8 + (((int)xy.y) >> 6));
        atomicAdd(&cntsm[cell], 1u);
    }
    __syncthreads();
    if (tid == 0) {
        unsigned run = 0;
        for (int c = 0; c < CELLS; c++) { startsm[c] = run; run += cntsm[c]; }
        startsm[CELLS] = run;
    }
    __syncthreads();
    if (tid < 64) {
        cursm[tid] = startsm[tid];
        g_cnt[sb * CELLS + tid] = (int)cntsm[tid];
    }
    __syncthreads();
    #pragma unroll
    for (int i = tid; i < NPTS; i += 512) {
        float2 xy = *(const float2*)(drags + 2 * i);
        unsigned cell = (unsigned)((((int)xy.x) >> 6) * 8 + (((int)xy.y) >> 6));
        unsigned pos = atomicAdd(&cursm[cell], 1u);
        ordsm[pos] = (unsigned short)i;
        csort[pos] = (unsigned char)cell;
    }
    __syncthreads();

    const int pairid = w >> 1;
    const int half   = w & 1;
    float* htile = h1s + pairid * 2048;        // 16 rows x 128 f
    float* myfts = htile + half * 1024;        // aliases own 8 rows

    u64 b1r0 = *(const u64*)(b1 + 4 * l);
    u64 b1r1 = *(const u64*)(b1 + 4 * l + 2);
    const int colbase = 128 * half + 4 * l;
    u64 b2ra = *(const u64*)(b2 + colbase);
    u64 b2rb = *(const u64*)(b2 + colbase + 2);

    const float fr      = c_freq[l >> 2];
    const int   use_y   = l & 1;
    const int   use_cos = (l >> 1) & 1;
    const int   barid   = 1 + pairid;

    u64 run0 = 0, run1 = 0;
    int cur_cell = -1;

    // prologue: fv for tile b=0
    float fv[8];
    #pragma unroll
    for (int pp = 0; pp < 8; pp++) {
        int idx = (int)ordsm[128 * pairid + 8 * half + pp];
        float2 xy = *(const float2*)(drags + 2 * idx);
        fv[pp] = trig_red((use_y ? xy.y : xy.x) * fr, use_cos);
    }

    #pragma unroll 1
    for (int b = 0; b < 8; b++) {
        const int p0 = 128 * pairid + 16 * b;

        // publish current tile's features
        #pragma unroll
        for (int pp = 0; pp < 8; pp++) myfts[pp * 32 + l] = fv[pp];
        __syncwarp();

        u64 a1[8][2];
        #pragma unroll
        for (int pp = 0; pp < 8; pp++) { a1[pp][0] = b1r0; a1[pp][1] = b1r1; }
        #pragma unroll 4
        for (int k2 = 0; k2 < 16; k2++) {
            float2 f01[8];
            #pragma unroll
            for (int pp = 0; pp < 8; pp++)
                f01[pp] = *(const float2*)(myfts + pp * 32 + 2 * k2);
            #pragma unroll
            for (int s = 0; s < 2; s++) {
                const int k = 2 * k2 + s;
                ulonglong2 wv = *(const ulonglong2*)(W1s + k * 128 + 4 * l);
                #pragma unroll
                for (int pp = 0; pp < 8; pp++) {
                    u64 f2 = dup2(s ? f01[pp].y : f01[pp].x);
                    a1[pp][0] = ffma2(f2, wv.x, a1[pp][0]);
                    a1[pp][1] = ffma2(f2, wv.y, a1[pp][1]);
                }
            }
        }
        __syncwarp();
        #pragma unroll
        for (int pp = 0; pp < 8; pp++) {
            float2 v0 = un2(a1[pp][0]), v1 = un2(a1[pp][1]);
            float4 hv = make_float4(silu_f(v0.x), silu_f(v0.y),
                                    silu_f(v1.x), silu_f(v1.y));
            *(float4*)(htile + (8 * half + pp) * 128 + 4 * l) = hv;
        }
        pair_bar(barid);

        // prefetch NEXT tile's points + trig; LDG+MUFU hide under L2 FMA below
        if (b < 7) {
            #pragma unroll
            for (int pp = 0; pp < 8; pp++) {
                int idx = (int)ordsm[p0 + 16 + 8 * half + pp];
                float2 xy = *(const float2*)(drags + 2 * idx);
                fv[pp] = trig_red((use_y ? xy.y : xy.x) * fr, use_cos);
            }
        }

        u64 acc[16][2];
        #pragma unroll
        for (int pp = 0; pp < 16; pp++) { acc[pp][0] = b2ra; acc[pp][1] = b2rb; }
        #pragma unroll 1
        for (int kq = 0; kq < 32; kq++) {
            const float* wr = W2s + (4 * kq) * 256 + colbase;
            ulonglong2 wv0 = *(const ulonglong2*)(wr);
            ulonglong2 wv1 = *(const ulonglong2*)(wr + 256);
            ulonglong2 wv2 = *(const ulonglong2*)(wr + 512);
            ulonglong2 wv3 = *(const ulonglong2*)(wr + 768);
            const float* hb = htile + 4 * kq;
            #pragma unroll
            for (int pp = 0; pp < 16; pp++) {
                float4 h4 = *(const float4*)(hb + pp * 128);
                acc[pp][0] = ffma2(dup2(h4.x), wv0.x, acc[pp][0]);
                acc[pp][1] = ffma2(dup2(h4.x), wv0.y, acc[pp][1]);
                acc[pp][0] = ffma2(dup2(h4.y), wv1.x, acc[pp][0]);
                acc[pp][1] = ffma2(dup2(h4.y), wv1.y, acc[pp][1]);
                acc[pp][0] = ffma2(dup2(h4.z), wv2.x, acc[pp][0]);
                acc[pp][1] = ffma2(dup2(h4.z), wv2.y, acc[pp][1]);
                acc[pp][0] = ffma2(dup2(h4.w), wv3.x, acc[pp][0]);
                acc[pp][1] = ffma2(dup2(h4.w), wv3.y, acc[pp][1]);
            }
        }

        #pragma unroll
        for (int pp = 0; pp < 16; pp++) {
            int c = (int)csort[p0 + pp];
            if (c != cur_cell) {
                if (cur_cell >= 0) {
                    float* gp = gbase + (size_t)cur_cell * D2 + colbase;
                    float2 v0 = un2(run0), v1 = un2(run1);
                    atomicAdd(gp,     v0.x); atomicAdd(gp + 1, v0.y);
                    atomicAdd(gp + 2, v1.x); atomicAdd(gp + 3, v1.y);
                }
                cur_cell = c;
                run0 = run1 = 0;
            }
            run0 = fadd2(run0, silu2(acc[pp][0]));
            run1 = fadd2(run1, silu2(acc[pp][1]));
        }
        pair_bar(barid);
    }
    if (cur_cell >= 0) {
        float* gp = gbase + (size_t)cur_cell * D2 + colbase;
        float2 v0 = un2(run0), v1 = un2(run1);
        atomicAdd(gp,     v0.x); atomicAdd(gp + 1, v0.y);
        atomicAdd(gp + 2, v1.x); atomicAdd(gp + 3, v1.y);
    }
}

// ---------------- K2 smem layout — R12 + single-sync ring ----------------
#define S2_W3A 0        // 65536 (32 rows * 512 f)
#define S2_W3B 65536    // 65536
#define S2_HST 131072   // 66560 (256 * 65 f, padded transpose)
#define S2_B3  197632   // 2048
#define S2_CNT 199680   // 256
#define SMEM2  199936

// out = Hsum @ W3 + cnt*b3. Warp w owns cols [32w,32w+32); lane l owns
// cells l, l+32. W3 double-buffered via cp.async; ONE sync per tile:
// wait(kt) -> sync -> prefetch kt+1 (buffer last read at kt-1; all warps
// provably past it) -> compute kt.
__global__ __launch_bounds__(512, 1)
void k2_l3(const float* __restrict__ W3, const float* __restrict__ b3,
           float* __restrict__ out)
{
    extern __shared__ char smem[];
    float* w3a  = (float*)(smem + S2_W3A);
    float* w3b  = (float*)(smem + S2_W3B);
    float* Hst  = (float*)(smem + S2_HST);
    float* b3s  = (float*)(smem + S2_B3);
    float* cnts = (float*)(smem + S2_CNT);

    const int tid = threadIdx.x;
    const int w   = tid >> 5;
    const int l   = tid & 31;
    const int sb  = blockIdx.x;
    const int side = sb >> 6;
    const int bv   = sb & 63;

    const unsigned sa = smem_u32(w3a);
    const unsigned sbuf[2] = { sa, sa + 65536u };

    // prefetch tile 0
    {
        const char* g0 = (const char*)W3;
        #pragma unroll
        for (int j = 0; j < 8; j++) {
            int f4 = tid + j * 512;
            cpa16(sbuf[0] + f4 * 16, g0 + (size_t)f4 * 16);
        }
        asm volatile("cp.async.commit_group;");
    }

    // stage transposed H: Hst[k*65 + cell] = g_hsum[sb][cell][k]
    {
        const float* src = g_hsum + (size_t)sb * CELLS * D2;
        for (int base = tid; base < CELLS * D2; base += 512) {
            int cell = base >> 8;
            int k    = base & 255;
            Hst[k * 65 + cell] = src[base];
        }
        b3s[tid] = b3[tid];
        if (tid < 64) cnts[tid] = (float)g_cnt[sb * CELLS + tid];
    }

    u64 acc[2][16];
    #pragma unroll
    for (int h = 0; h < 2; h++)
        #pragma unroll
        for (int j = 0; j < 16; j++) acc[h][j] = 0ull;

    #pragma unroll 1
    for (int kt = 0; kt < 8; kt++) {
        asm volatile("cp.async.wait_group 0;");
        __syncthreads();
        if (kt < 7) {   // prefetch next tile; overlaps compute below
            const char* gn = (const char*)(W3 + (size_t)(kt + 1) * 32 * D3);
            #pragma unroll
            for (int j = 0; j < 8; j++) {
                int f4 = tid + j * 512;
                cpa16(sbuf[(kt + 1) & 1] + f4 * 16, gn + (size_t)f4 * 16);
            }
            asm volatile("cp.async.commit_group;");
        }

        const float* wt = (kt & 1) ? w3b : w3a;
        #pragma unroll 2
        for (int kk = 0; kk < 32; kk++) {
            const int k = kt * 32 + kk;
            u64 hd0 = dup2(Hst[k * 65 + l]);
            u64 hd1 = dup2(Hst[k * 65 + l + 32]);
            const float* wr = wt + kk * D3 + 32 * w;
            #pragma unroll
            for (int j2 = 0; j2 < 8; j2++) {   // broadcast LDS.128
                ulonglong2 wv = *(const ulonglong2*)(wr + 4 * j2);
                acc[0][2 * j2]     = ffma2(hd0, wv.x, acc[0][2 * j2]);
                acc[0][2 * j2 + 1] = ffma2(hd0, wv.y, acc[0][2 * j2 + 1]);
                acc[1][2 * j2]     = ffma2(hd1, wv.x, acc[1][2 * j2]);
                acc[1][2 * j2 + 1] = ffma2(hd1, wv.y, acc[1][2 * j2 + 1]);
            }
        }
    }

    const float c0 = cnts[l], c1 = cnts[l + 32];
    float* outp = out + ((size_t)(bv * 1024 + side * 512)) * 64;
    #pragma unroll
    for (int j = 0; j < 16; j++) {
        int col = 32 * w + 2 * j;
        float bx = b3s[col], by = b3s[col + 1];
        float2 v0 = un2(acc[0][j]);
        float2 v1 = un2(acc[1][j]);
        outp[(size_t)col       * 64 + l]      = v0.x + c0 * bx;
        outp[(size_t)(col + 1) * 64 + l]      = v0.y + c0 * by;
        outp[(size_t)col       * 64 + l + 32] = v1.x + c1 * bx;
        outp[(size_t)(col + 1) * 64 + l + 32] = v1.y + c1 * by;
    }
}

extern "C" void kernel_launch(void* const* d_in, const int* in_sizes, int n_in,
                              void* d_out, int out_size)
{
    const float* ds = (const float*)d_in[0];
    const float* de = (const float*)d_in[1];
    const float* W1 = (const float*)d_in[2];
    const float* b1 = (const float*)d_in[3];
    const float* W2 = (const float*)d_in[4];
    const float* b2 = (const float*)d_in[5];
    const float* W3 = (const float*)d_in[6];
    const float* b3 = (const float*)d_in[7];
    float* out = (float*)d_out;

    cudaFuncSetAttribute(k1_embed_agg, cudaFuncAttributeMaxDynamicSharedMemorySize, SMEM1);
    cudaFuncSetAttribute(k2_l3,        cudaFuncAttributeMaxDynamicSharedMemorySize, SMEM2);

    k1_embed_agg<<<SBCNT, 512, SMEM1>>>(ds, de, W1, b1, W2, b2);
    k2_l3<<<SBCNT, 512, SMEM2>>>(W3, b3, out);
}

// round 16
// speedup vs baseline: 1.6200x; 1.0718x over previous
#include <cuda_runtime.h>
#include <math.h>

#define NPTS  1024
#define D2    256
#define D3    512
#define CELLS 64
#define SBCNT 128

__device__ float g_hsum[SBCNT * CELLS * D2];
__device__ int   g_cnt [SBCNT * CELLS];

__constant__ float c_freq[8] = {
    1.0f, 1.7782794100389228f, 3.1622776601683795f, 5.623413251903491f,
    10.0f, 17.782794100389228f, 31.622776601683793f, 56.23413251903491f
};

typedef unsigned long long u64;

__device__ __forceinline__ u64 pk2(float lo, float hi) {
    u64 r; asm("mov.b64 %0,{%1,%2};" : "=l"(r) : "f"(lo), "f"(hi)); return r;
}
__device__ __forceinline__ u64 dup2(float v) { return pk2(v, v); }
__device__ __forceinline__ u64 ffma2(u64 a, u64 b, u64 c) {
    u64 d; asm("fma.rn.f32x2 %0,%1,%2,%3;" : "=l"(d) : "l"(a), "l"(b), "l"(c)); return d;
}
__device__ __forceinline__ u64 fadd2(u64 a, u64 b) {
    u64 d; asm("add.rn.f32x2 %0,%1,%2;" : "=l"(d) : "l"(a), "l"(b)); return d;
}
__device__ __forceinline__ float2 un2(u64 v) {
    float2 f; asm("mov.b64 {%0,%1},%2;" : "=f"(f.x), "=f"(f.y) : "l"(v)); return f;
}
// silu via 1 MUFU: x*sigmoid(x) = 0.5x*(1+tanh(0.5x))
__device__ __forceinline__ float silu_f(float v) {
    float h = 0.5f * v;
    float t; asm("tanh.approx.f32 %0, %1;" : "=f"(t) : "f"(h));
    return __fmaf_rn(h, t, h);
}
__device__ __forceinline__ u64 silu2(u64 a) {
    float2 v = un2(a); return pk2(silu_f(v.x), silu_f(v.y));
}
// Cody-Waite mod-2pi then MUFU trig (arg reduced to [-pi,pi])
__device__ __forceinline__ float trig_red(float arg, int use_cos) {
    const float INV2PI = 0.15915494309189535f;
    const float C_HI   = 6.2831854820251465f;
    const float C_LO   = -1.7484556e-7f;
    float q = rintf(arg * INV2PI);
    float r = __fmaf_rn(-q, C_HI, arg);
    r = __fmaf_rn(-q, C_LO, r);
    return use_cos ? __cosf(r) : __sinf(r);
}

__device__ __forceinline__ unsigned smem_u32(const void* p) {
    return (unsigned)__cvta_generic_to_shared(p);
}
__device__ __forceinline__ void cpa16(unsigned s, const void* g) {
    asm volatile("cp.async.cg.shared.global [%0], [%1], 16;" :: "r"(s), "l"(g));
}
__device__ __forceinline__ void pair_bar(int id) {
    asm volatile("bar.sync %0, 64;" :: "r"(id) : "memory");
}

// ---------------- K1 smem layout (bytes) — R12 structure ----------------
#define S1_W2    0          // 131072
#define S1_W1    131072     // 16384
#define S1_H1    147456     // 65536  (8 pairs * 16 pts * 128 f; fts aliases)
#define S1_ORD   212992     // 2048   (u16[1024])
#define S1_CSORT 215040     // 1024   (u8[1024])
#define S1_CNT   216064     // 256
#define S1_START 216320     // 272
#define S1_CUR   216592     // 256
#define SMEM1    216848

__global__ __launch_bounds__(512, 1)
void k1_embed_agg(const float* __restrict__ ds, const float* __restrict__ de,
                  const float* __restrict__ W1, const float* __restrict__ b1,
                  const float* __restrict__ W2, const float* __restrict__ b2)
{
    extern __shared__ char smem[];
    float*          W2s    = (float*)(smem + S1_W2);
    float*          W1s    = (float*)(smem + S1_W1);
    float*          h1s    = (float*)(smem + S1_H1);
    unsigned short* ordsm  = (unsigned short*)(smem + S1_ORD);
    unsigned char*  csort  = (unsigned char*)(smem + S1_CSORT);
    unsigned*       cntsm  = (unsigned*)(smem + S1_CNT);
    unsigned*       startsm= (unsigned*)(smem + S1_START);
    unsigned*       cursm  = (unsigned*)(smem + S1_CUR);

    const int tid = threadIdx.x;
    const int w   = tid >> 5;
    const int l   = tid & 31;
    const int sb  = blockIdx.x;
    const int side = sb >> 6;
    const int bv   = sb & 63;
    const float* __restrict__ drags = (side ? de : ds) + (size_t)bv * NPTS * 2;
    float* gbase = g_hsum + (size_t)sb * CELLS * D2;

    {
        const float4* src2 = (const float4*)W2;
        float4* dst2 = (float4*)W2s;
        #pragma unroll 4
        for (int i = tid; i < (128 * 256) / 4; i += 512) dst2[i] = src2[i];
        const float4* src1 = (const float4*)W1;
        float4* dst1 = (float4*)W1s;
        #pragma unroll
        for (int i = tid; i < (32 * 128) / 4; i += 512) dst1[i] = src1[i];
        float4* gz = (float4*)gbase;
        #pragma unroll
        for (int i = tid; i < (CELLS * D2) / 4; i += 512)
            gz[i] = make_float4(0.f, 0.f, 0.f, 0.f);
        if (tid < 64) cntsm[tid] = 0u;
    }
    __syncthreads();

    #pragma unroll
    for (int i = tid; i < NPTS; i += 512) {
        float2 xy = *(const float2*)(drags + 2 * i);
        unsigned cell = (unsigned)((((int)xy.x) >> 6) * 8 + (((int)xy.y) >> 6));
        atomicAdd(&cntsm[cell], 1u);
    }
    __syncthreads();
    if (tid == 0) {
        unsigned run = 0;
        for (int c = 0; c < CELLS; c++) { startsm[c] = run; run += cntsm[c]; }
        startsm[CELLS] = run;
    }
    __syncthreads();
    if (tid < 64) {
        cursm[tid] = startsm[tid];
        g_cnt[sb * CELLS + tid] = (int)cntsm[tid];
    }
    __syncthreads();
    #pragma unroll
    for (int i = tid; i < NPTS; i += 512) {
        float2 xy = *(const float2*)(drags + 2 * i);
        unsigned cell = (unsigned)((((int)xy.x) >> 6) * 8 + (((int)xy.y) >> 6));
        unsigned pos = atomicAdd(&cursm[cell], 1u);
        ordsm[pos] = (unsigned short)i;
        csort[pos] = (unsigned char)cell;
    }
    __syncthreads();

    const int pairid = w >> 1;
    const int half   = w & 1;
    float* htile = h1s + pairid * 2048;        // 16 rows x 128 f
    float* myfts = htile + half * 1024;        // aliases own 8 rows

    u64 b1r0 = *(const u64*)(b1 + 4 * l);
    u64 b1r1 = *(const u64*)(b1 + 4 * l + 2);
    const int colbase = 128 * half + 4 * l;
    u64 b2ra = *(const u64*)(b2 + colbase);
    u64 b2rb = *(const u64*)(b2 + colbase + 2);

    const float fr      = c_freq[l >> 2];
    const int   use_y   = l & 1;
    const int   use_cos = (l >> 1) & 1;
    const int   barid   = 1 + pairid;

    u64 run0 = 0, run1 = 0;
    int cur_cell = -1;

    #pragma unroll 1
    for (int b = 0; b < 8; b++) {
        const int p0 = 128 * pairid + 16 * b;

        float fv[8];
        #pragma unroll
        for (int pp = 0; pp < 8; pp++) {
            int idx = (int)ordsm[p0 + 8 * half + pp];
            float2 xy = *(const float2*)(drags + 2 * idx);
            fv[pp] = trig_red((use_y ? xy.y : xy.x) * fr, use_cos);
        }
        #pragma unroll
        for (int pp = 0; pp < 8; pp++) myfts[pp * 32 + l] = fv[pp];
        __syncwarp();

        u64 a1[8][2];
        #pragma unroll
        for (int pp = 0; pp < 8; pp++) { a1[pp][0] = b1r0; a1[pp][1] = b1r1; }
        #pragma unroll 2
        for (int k4 = 0; k4 < 8; k4++) {
            float4 f03[8];
            #pragma unroll
            for (int pp = 0; pp < 8; pp++)         // broadcast LDS.128, feeds 4 k's
                f03[pp] = *(const float4*)(myfts + pp * 32 + 4 * k4);
            #pragma unroll
            for (int s = 0; s < 4; s++) {
                const int k = 4 * k4 + s;
                ulonglong2 wv = *(const ulonglong2*)(W1s + k * 128 + 4 * l);
                #pragma unroll
                for (int pp = 0; pp < 8; pp++) {
                    float fc = (s == 0) ? f03[pp].x : (s == 1) ? f03[pp].y
                              : (s == 2) ? f03[pp].z : f03[pp].w;
                    u64 f2 = dup2(fc);
                    a1[pp][0] = ffma2(f2, wv.x, a1[pp][0]);
                    a1[pp][1] = ffma2(f2, wv.y, a1[pp][1]);
                }
            }
        }
        __syncwarp();
        #pragma unroll
        for (int pp = 0; pp < 8; pp++) {
            float2 v0 = un2(a1[pp][0]), v1 = un2(a1[pp][1]);
            float4 hv = make_float4(silu_f(v0.x), silu_f(v0.y),
                                    silu_f(v1.x), silu_f(v1.y));
            *(float4*)(htile + (8 * half + pp) * 128 + 4 * l) = hv;
        }
        pair_bar(barid);

        u64 acc[16][2];
        #pragma unroll
        for (int pp = 0; pp < 16; pp++) { acc[pp][0] = b2ra; acc[pp][1] = b2rb; }
        #pragma unroll 1
        for (int kq = 0; kq < 32; kq++) {
            const float* wr = W2s + (4 * kq) * 256 + colbase;
            ulonglong2 wv0 = *(const ulonglong2*)(wr);
            ulonglong2 wv1 = *(const ulonglong2*)(wr + 256);
            ulonglong2 wv2 = *(const ulonglong2*)(wr + 512);
            ulonglong2 wv3 = *(const ulonglong2*)(wr + 768);
            const float* hb = htile + 4 * kq;
            #pragma unroll
            for (int pp = 0; pp < 16; pp++) {
                float4 h4 = *(const float4*)(hb + pp * 128);
                acc[pp][0] = ffma2(dup2(h4.x), wv0.x, acc[pp][0]);
                acc[pp][1] = ffma2(dup2(h4.x), wv0.y, acc[pp][1]);
                acc[pp][0] = ffma2(dup2(h4.y), wv1.x, acc[pp][0]);
                acc[pp][1] = ffma2(dup2(h4.y), wv1.y, acc[pp][1]);
                acc[pp][0] = ffma2(dup2(h4.z), wv2.x, acc[pp][0]);
                acc[pp][1] = ffma2(dup2(h4.z), wv2.y, acc[pp][1]);
                acc[pp][0] = ffma2(dup2(h4.w), wv3.x, acc[pp][0]);
                acc[pp][1] = ffma2(dup2(h4.w), wv3.y, acc[pp][1]);
            }
        }

        #pragma unroll
        for (int pp = 0; pp < 16; pp++) {
            int c = (int)csort[p0 + pp];
            if (c != cur_cell) {
                if (cur_cell >= 0) {
                    float* gp = gbase + (size_t)cur_cell * D2 + colbase;
                    float2 v0 = un2(run0), v1 = un2(run1);
                    atomicAdd(gp,     v0.x); atomicAdd(gp + 1, v0.y);
                    atomicAdd(gp + 2, v1.x); atomicAdd(gp + 3, v1.y);
                }
                cur_cell = c;
                run0 = run1 = 0;
            }
            run0 = fadd2(run0, silu2(acc[pp][0]));
            run1 = fadd2(run1, silu2(acc[pp][1]));
        }
        pair_bar(barid);
    }
    if (cur_cell >= 0) {
        float* gp = gbase + (size_t)cur_cell * D2 + colbase;
        float2 v0 = un2(run0), v1 = un2(run1);
        atomicAdd(gp,     v0.x); atomicAdd(gp + 1, v0.y);
        atomicAdd(gp + 2, v1.x); atomicAdd(gp + 3, v1.y);
    }
}

// ---------------- K2 smem layout — single-sync cp.async ring ----------------
#define S2_W3A 0        // 65536 (32 rows * 512 f)
#define S2_W3B 65536    // 65536
#define S2_HST 131072   // 66560 (256 * 65 f, padded transpose)
#define S2_B3  197632   // 2048
#define S2_CNT 199680   // 256
#define SMEM2  199936

// out = Hsum @ W3 + cnt*b3. Warp w owns cols [32w,32w+32); lane l owns
// cells l, l+32. ONE sync per tile: wait(kt) -> sync -> prefetch kt+1
// (buffer last read at kt-1; all warps provably past it) -> compute kt.
__global__ __launch_bounds__(512, 1)
void k2_l3(const float* __restrict__ W3, const float* __restrict__ b3,
           float* __restrict__ out)
{
    extern __shared__ char smem[];
    float* w3a  = (float*)(smem + S2_W3A);
    float* w3b  = (float*)(smem + S2_W3B);
    float* Hst  = (float*)(smem + S2_HST);
    float* b3s  = (float*)(smem + S2_B3);
    float* cnts = (float*)(smem + S2_CNT);

    const int tid = threadIdx.x;
    const int w   = tid >> 5;
    const int l   = tid & 31;
    const int sb  = blockIdx.x;
    const int side = sb >> 6;
    const int bv   = sb & 63;

    const unsigned sa = smem_u32(w3a);
    const unsigned sbuf[2] = { sa, sa + 65536u };

    // prefetch tile 0
    {
        const char* g0 = (const char*)W3;
        #pragma unroll
        for (int j = 0; j < 8; j++) {
            int f4 = tid + j * 512;
            cpa16(sbuf[0] + f4 * 16, g0 + (size_t)f4 * 16);
        }
        asm volatile("cp.async.commit_group;");
    }

    // stage transposed H: Hst[k*65 + cell] = g_hsum[sb][cell][k]
    {
        const float* src = g_hsum + (size_t)sb * CELLS * D2;
        for (int base = tid; base < CELLS * D2; base += 512) {
            int cell = base >> 8;
            int k    = base & 255;
            Hst[k * 65 + cell] = src[base];
        }
        b3s[tid] = b3[tid];
        if (tid < 64) cnts[tid] = (float)g_cnt[sb * CELLS + tid];
    }

    u64 acc[2][16];
    #pragma unroll
    for (int h = 0; h < 2; h++)
        #pragma unroll
        for (int j = 0; j < 16; j++) acc[h][j] = 0ull;

    #pragma unroll 1
    for (int kt = 0; kt < 8; kt++) {
        asm volatile("cp.async.wait_group 0;");
        __syncthreads();
        if (kt < 7) {   // prefetch next tile; overlaps compute below
            const char* gn = (const char*)(W3 + (size_t)(kt + 1) * 32 * D3);
            #pragma unroll
            for (int j = 0; j < 8; j++) {
                int f4 = tid + j * 512;
                cpa16(sbuf[(kt + 1) & 1] + f4 * 16, gn + (size_t)f4 * 16);
            }
            asm volatile("cp.async.commit_group;");
        }

        const float* wt = (kt & 1) ? w3b : w3a;
        #pragma unroll 2
        for (int kk = 0; kk < 32; kk++) {
            const int k = kt * 32 + kk;
            u64 hd0 = dup2(Hst[k * 65 + l]);
            u64 hd1 = dup2(Hst[k * 65 + l + 32]);
            const float* wr = wt + kk * D3 + 32 * w;
            #pragma unroll
            for (int j2 = 0; j2 < 8; j2++) {   // broadcast LDS.128
                ulonglong2 wv = *(const ulonglong2*)(wr + 4 * j2);
                acc[0][2 * j2]     = ffma2(hd0, wv.x, acc[0][2 * j2]);
                acc[0][2 * j2 + 1] = ffma2(hd0, wv.y, acc[0][2 * j2 + 1]);
                acc[1][2 * j2]     = ffma2(hd1, wv.x, acc[1][2 * j2]);
                acc[1][2 * j2 + 1] = ffma2(hd1, wv.y, acc[1][2 * j2 + 1]);
            }
        }
    }

    const float c0 = cnts[l], c1 = cnts[l + 32];
    float* outp = out + ((size_t)(bv * 1024 + side * 512)) * 64;
    #pragma unroll
    for (int j = 0; j < 16; j++) {
        int col = 32 * w + 2 * j;
        float bx = b3s[col], by = b3s[col + 1];
        float2 v0 = un2(acc[0][j]);
        float2 v1 = un2(acc[1][j]);
        outp[(size_t)col       * 64 + l]      = v0.x + c0 * bx;
        outp[(size_t)(col + 1) * 64 + l]      = v0.y + c0 * by;
        outp[(size_t)col       * 64 + l + 32] = v1.x + c1 * bx;
        outp[(size_t)(col + 1) * 64 + l + 32] = v1.y + c1 * by;
    }
}

extern "C" void kernel_launch(void* const* d_in, const int* in_sizes, int n_in,
                              void* d_out, int out_size)
{
    const float* ds = (const float*)d_in[0];
    const float* de = (const float*)d_in[1];
    const float* W1 = (const float*)d_in[2];
    const float* b1 = (const float*)d_in[3];
    const float* W2 = (const float*)d_in[4];
    const float* b2 = (const float*)d_in[5];
    const float* W3 = (const float*)d_in[6];
    const float* b3 = (const float*)d_in[7];
    float* out = (float*)d_out;

    cudaFuncSetAttribute(k1_embed_agg, cudaFuncAttributeMaxDynamicSharedMemorySize, SMEM1);
    cudaFuncSetAttribute(k2_l3,        cudaFuncAttributeMaxDynamicSharedMemorySize, SMEM2);

    k1_embed_agg<<<SBCNT, 512, SMEM1>>>(ds, de, W1, b1, W2, b2);
    k2_l3<<<SBCNT, 512, SMEM2>>>(W3, b3, out);
}